// round 13
// baseline (speedup 1.0000x reference)
#include <cuda_runtime.h>
#include <math.h>

#define CC 8
#define HH 256
#define WW 256
#define BB 8
#define NB 4
#define TX 32
#define TYF 16            // tile height (2 core pixels per thread)
#define TYH 8             // vertical split
#define NT 256

// scratch (no allocations allowed): f features + d1 ping-pong
__device__ float g_f[(size_t)BB*CC*HH*WW];
__device__ float g_d1[2][(size_t)BB*CC*HH*WW];

// ---------------------------------------------------------------------------
// Stage A: f = conv(d1, We); w1 = paconv(f, Wp) * f; x1 = softargmax(d1, w1)
// Truly-sequential per-pixel paconv (#pragma unroll 1 prevents ptxas from
// fusing both pixel contexts); (256,3) -> 80-reg cap, 3 CTAs/SM.
// ---------------------------------------------------------------------------
__global__ __launch_bounds__(NT, 3) void k_stage_a(
    const float* __restrict__ d1_ext, int src,
    const float* __restrict__ We, const float* __restrict__ Wp,
    float* __restrict__ out, int blk)
{
    __shared__ float s_d1[CC][TYF+4][TX+4];   // halo 2
    __shared__ float s_f [CC][TYF+2][TX+2];   // halo 1
    __shared__ __align__(16) float s_We[CC*9*CC];   // [c][k][o]
    __shared__ __align__(16) float s_Wp[CC*9*CC];   // [c][k][o]

    const int tid = threadIdx.x;
    const int b  = blockIdx.z;
    const int x0 = blockIdx.x * TX;
    const int y0 = blockIdx.y * TYF;

    const float* d1p = d1_ext ? d1_ext : &g_d1[src][0];
    const float* d1b = d1p + (size_t)b * CC * HH * WW;

    for (int i = tid; i < CC*CC*9; i += NT) {
        int o = i / 72, r = i % 72, c = r / 9, k = r % 9;
        s_We[c*72 + k*8 + o] = We[i];
        s_Wp[c*72 + k*8 + o] = Wp[i];
    }

    for (int i = tid; i < CC*(TYF+4)*(TX+4); i += NT) {
        int c  = i / ((TYF+4)*(TX+4));
        int r  = i % ((TYF+4)*(TX+4));
        int ly = r / (TX+4), lx = r % (TX+4);
        int gy = y0 + ly - 2, gx = x0 + lx - 2;
        float v = 0.f;
        if (gy >= 0 && gy < HH && gx >= 0 && gx < WW)
            v = d1b[((size_t)c*HH + gy)*WW + gx];
        s_d1[c][ly][lx] = v;
    }
    __syncthreads();

    // f on halo-1 extended tile (zero outside image); grid-stride, NOT unrolled
    #pragma unroll 1
    for (int i = tid; i < (TYF+2)*(TX+2); i += NT) {
        int ly = i / (TX+2), lx = i % (TX+2);
        int gy = y0 + ly - 1, gx = x0 + lx - 1;
        float a0 = 0.f, a1 = 0.f, a2 = 0.f, a3 = 0.f;
        float a4 = 0.f, a5 = 0.f, a6 = 0.f, a7 = 0.f;
        if (gy >= 0 && gy < HH && gx >= 0 && gx < WW) {
            #pragma unroll
            for (int c = 0; c < CC; c++) {
                #pragma unroll
                for (int k = 0; k < 9; k++) {
                    float v = s_d1[c][ly + k/3][lx + k%3];
                    float4 wa = *(const float4*)&s_We[c*72 + k*8];
                    float4 wb = *(const float4*)&s_We[c*72 + k*8 + 4];
                    a0 = fmaf(v, wa.x, a0); a1 = fmaf(v, wa.y, a1);
                    a2 = fmaf(v, wa.z, a2); a3 = fmaf(v, wa.w, a3);
                    a4 = fmaf(v, wb.x, a4); a5 = fmaf(v, wb.y, a5);
                    a6 = fmaf(v, wb.z, a6); a7 = fmaf(v, wb.w, a7);
                }
            }
        }
        s_f[0][ly][lx] = a0; s_f[1][ly][lx] = a1;
        s_f[2][ly][lx] = a2; s_f[3][ly][lx] = a3;
        s_f[4][ly][lx] = a4; s_f[5][ly][lx] = a5;
        s_f[6][ly][lx] = a6; s_f[7][ly][lx] = a7;
    }
    __syncthreads();

    const int tyBase = tid / TX, tx = tid % TX;
    const int gx = x0 + tx;
    float* fo = g_f + (size_t)b * CC * HH * WW;

    // two core pixels processed TRULY sequentially (unroll suppressed so the
    // two pixel contexts are never live simultaneously)
    #pragma unroll 1
    for (int p = 0; p < 2; p++) {
        const int ty = tyBase + p * TYH;

        float fc[CC];
        #pragma unroll
        for (int c = 0; c < CC; c++) fc[c] = s_f[c][ty+1][tx+1];

        float a0 = 0.f, a1 = 0.f, a2 = 0.f, a3 = 0.f;
        float a4 = 0.f, a5 = 0.f, a6 = 0.f, a7 = 0.f;

        #pragma unroll
        for (int k = 0; k < 9; k++) {
            const int dy = k/3, dx = k%3;
            float pv[CC];
            float s = 0.f;
            #pragma unroll
            for (int c = 0; c < CC; c++) {
                pv[c] = s_f[c][ty+dy][tx+dx];
                float d = pv[c] - fc[c];
                s = fmaf(d, d, s);
            }
            float kern = __expf(-0.5f * s);
            #pragma unroll
            for (int c = 0; c < CC; c++) {
                float v = pv[c] * kern;
                float4 wa = *(const float4*)&s_Wp[c*72 + k*8];
                float4 wb = *(const float4*)&s_Wp[c*72 + k*8 + 4];
                a0 = fmaf(v, wa.x, a0); a1 = fmaf(v, wa.y, a1);
                a2 = fmaf(v, wa.z, a2); a3 = fmaf(v, wa.w, a3);
                a4 = fmaf(v, wb.x, a4); a5 = fmaf(v, wb.y, a5);
                a6 = fmaf(v, wb.z, a6); a7 = fmaf(v, wb.w, a7);
            }
        }

        float w1[CC];
        w1[0] = a0*fc[0]*10.f; w1[1] = a1*fc[1]*10.f;
        w1[2] = a2*fc[2]*10.f; w1[3] = a3*fc[3]*10.f;
        w1[4] = a4*fc[4]*10.f; w1[5] = a5*fc[5]*10.f;
        w1[6] = a6*fc[6]*10.f; w1[7] = a7*fc[7]*10.f;
        float m = -1e30f;
        #pragma unroll
        for (int c = 0; c < CC; c++) m = fmaxf(m, w1[c]);
        float se = 0.f, sd = 0.f;
        #pragma unroll
        for (int c = 0; c < CC; c++) {
            float e = __expf(w1[c] - m);
            se += e;
            sd = fmaf(e, s_d1[c][ty+2][tx+2], sd);
        }
        const int gy = y0 + ty;
        out[(((size_t)b*NB + blk)*HH + gy)*WW + gx] = sd / se;
        #pragma unroll
        for (int c = 0; c < CC; c++)
            fo[((size_t)c*HH + gy)*WW + gx] = fc[c];
    }
}

// ---------------------------------------------------------------------------
// Stage B (unchanged from R10 winner): smem aliased to 48.96KB, 4 CTAs/SM.
// ---------------------------------------------------------------------------
#define NB_D1   (CC*(TYF+4)*(TX+4))   // 5760  (s_da; later aliased by s_f)
#define NB_X1   ((TYF+4)*(TX+4))      // 720
#define NB_F    (CC*(TYF+2)*(TX+2))   // 4896  (fits inside NB_D1 region)
#define SMEM_B_BYTES ((NB_D1 + NB_X1 + NB_F + 576 + 288) * 4)   // 48,960

#define SDA(c,y,x) s_da[((c)*(TYF+4) + (y))*(TX+4) + (x)]
#define SX1(y,x)   s_x1[(y)*(TX+4) + (x)]
#define SF(c,y,x)  s_f [((c)*(TYF+2) + (y))*(TX+2) + (x)]
#define SFX(c,y,x) s_fx[((c)*(TYF+2) + (y))*(TX+2) + (x)]

__global__ __launch_bounds__(NT, 4) void k_stage_b(
    const float* __restrict__ d1_ext, int src, int dst,
    const float* __restrict__ x1base,
    const float* __restrict__ We2, const float* __restrict__ Wg)
{
    extern __shared__ __align__(16) float smem[];
    float* s_da  = smem;                 // |d1 - x1| halo-2; dead after fx conv
    float* s_f   = smem;                 // ALIAS: f halo-1, loaded after fx conv
    float* s_x1  = s_da + NB_D1;
    float* s_fx  = s_x1 + NB_X1;
    float* s_We2 = s_fx + NB_F;
    float4* s_Wg4 = (float4*)(s_We2 + 576);

    const int tid = threadIdx.x;
    const int b  = blockIdx.z;
    const int x0 = blockIdx.x * TX;
    const int y0 = blockIdx.y * TYF;

    const float* d1p = d1_ext ? d1_ext : &g_d1[src][0];
    const float* d1b = d1p + (size_t)b * CC * HH * WW;
    const float* x1b = x1base + (size_t)b * NB * HH * WW;
    const float* fb  = g_f + (size_t)b * CC * HH * WW;

    // phase 0: weights + x1 halo-2
    for (int i = tid; i < CC*CC*9; i += NT) {
        int o = i / 72, r = i % 72, c = r / 9, k = r % 9;
        s_We2[c*72 + k*8 + o] = We2[i];
    }
    for (int i = tid; i < CC*9; i += NT) {
        int g = i / 9, k = i % 9;
        s_Wg4[i] = make_float4(Wg[(g*2+0)*18 + k], Wg[(g*2+0)*18 + 9 + k],
                               Wg[(g*2+1)*18 + k], Wg[(g*2+1)*18 + 9 + k]);
    }
    for (int i = tid; i < NB_X1; i += NT) {
        int ly = i / (TX+4), lx = i % (TX+4);
        int gy = y0 + ly - 2, gx = x0 + lx - 2;
        float v = 0.f;
        if (gy >= 0 && gy < HH && gx >= 0 && gx < WW)
            v = x1b[(size_t)gy*WW + gx];
        SX1(ly, lx) = v;
    }
    __syncthreads();

    // phase 1: s_da = |d1 - x1| (out-of-image |0-0|=0 matches zero-pad)
    for (int i = tid; i < NB_D1; i += NT) {
        int c  = i / ((TYF+4)*(TX+4));
        int r  = i % ((TYF+4)*(TX+4));
        int ly = r / (TX+4), lx = r % (TX+4);
        int gy = y0 + ly - 2, gx = x0 + lx - 2;
        float v = 0.f;
        if (gy >= 0 && gy < HH && gx >= 0 && gx < WW)
            v = fabsf(d1b[((size_t)c*HH + gy)*WW + gx] - s_x1[r]);
        s_da[i] = v;
    }
    __syncthreads();

    // phase 2: fx = conv(s_da, We2) on halo-1 extended tile -> s_fx
    for (int i = tid; i < (TYF+2)*(TX+2); i += NT) {
        int ly = i / (TX+2), lx = i % (TX+2);
        int gy = y0 + ly - 1, gx = x0 + lx - 1;
        float a0 = 0.f, a1 = 0.f, a2 = 0.f, a3 = 0.f;
        float a4 = 0.f, a5 = 0.f, a6 = 0.f, a7 = 0.f;
        if (gy >= 0 && gy < HH && gx >= 0 && gx < WW) {
            #pragma unroll
            for (int c = 0; c < CC; c++) {
                #pragma unroll
                for (int k = 0; k < 9; k++) {
                    float v = SDA(c, ly + k/3, lx + k%3);
                    float4 wa = *(const float4*)&s_We2[c*72 + k*8];
                    float4 wb = *(const float4*)&s_We2[c*72 + k*8 + 4];
                    a0 = fmaf(v, wa.x, a0); a1 = fmaf(v, wa.y, a1);
                    a2 = fmaf(v, wa.z, a2); a3 = fmaf(v, wa.w, a3);
                    a4 = fmaf(v, wb.x, a4); a5 = fmaf(v, wb.y, a5);
                    a6 = fmaf(v, wb.z, a6); a7 = fmaf(v, wb.w, a7);
                }
            }
        }
        SFX(0, ly, lx) = a0; SFX(1, ly, lx) = a1;
        SFX(2, ly, lx) = a2; SFX(3, ly, lx) = a3;
        SFX(4, ly, lx) = a4; SFX(5, ly, lx) = a5;
        SFX(6, ly, lx) = a6; SFX(7, ly, lx) = a7;
    }
    __syncthreads();   // s_da fully consumed

    // phase 2b: load f halo-1 into the aliased buffer
    for (int i = tid; i < NB_F; i += NT) {
        int c  = i / ((TYF+2)*(TX+2));
        int r  = i % ((TYF+2)*(TX+2));
        int ly = r / (TX+2), lx = r % (TX+2);
        int gy = y0 + ly - 1, gx = x0 + lx - 1;
        float v = 0.f;
        if (gy >= 0 && gy < HH && gx >= 0 && gx < WW)
            v = fb[((size_t)c*HH + gy)*WW + gx];
        s_f[i] = v;
    }
    __syncthreads();

    // phase 3: grouped paconv + blend; 2 core pixels/thread (split pairing)
    const int tyA = tid / TX, tx = tid % TX;
    const int tyB = tyA + TYH;
    const int gx = x0 + tx;
    const int gyA = y0 + tyA, gyB = y0 + tyB;
    const float x1A = SX1(tyA+2, tx+2);
    const float x1B = SX1(tyB+2, tx+2);
    float* dout = &g_d1[dst][0] + (size_t)b * CC * HH * WW;

    #pragma unroll
    for (int g = 0; g < CC; g++) {
        const float cfA  = SF (g, tyA+1, tx+1);
        const float cfxA = SFX(g, tyA+1, tx+1);
        const float cfB  = SF (g, tyB+1, tx+1);
        const float cfxB = SFX(g, tyB+1, tx+1);
        float w0A = 0.f, w1A = 0.f, w0B = 0.f, w1B = 0.f;
        #pragma unroll
        for (int k = 0; k < 9; k++) {
            const int dy = k/3, dx = k%3;
            float4 w = s_Wg4[g*9 + k];
            float pfA  = SF (g, tyA+dy, tx+dx);
            float pfxA = SFX(g, tyA+dy, tx+dx);
            float dfA = pfA - cfA, dfxA = pfxA - cfxA;
            float kernA = __expf(-0.5f * fmaf(dfA, dfA, dfxA*dfxA));
            w0A = fmaf(kernA, fmaf(pfA, w.x, pfxA * w.y), w0A);
            w1A = fmaf(kernA, fmaf(pfA, w.z, pfxA * w.w), w1A);

            float pfB  = SF (g, tyB+dy, tx+dx);
            float pfxB = SFX(g, tyB+dy, tx+dx);
            float dfB = pfB - cfB, dfxB = pfxB - cfxB;
            float kernB = __expf(-0.5f * fmaf(dfB, dfB, dfxB*dfxB));
            w0B = fmaf(kernB, fmaf(pfB, w.x, pfxB * w.y), w0B);
            w1B = fmaf(kernB, fmaf(pfB, w.z, pfxB * w.w), w1B);
        }
        float sA = 1.f / (1.f + __expf(-2.0f * (w1A - w0A)));
        float sB = 1.f / (1.f + __expf(-2.0f * (w1B - w0B)));
        // original d1 centers from global (smem holds f, not d1)
        float dA = d1b[((size_t)g*HH + gyA)*WW + gx];
        float dB = d1b[((size_t)g*HH + gyB)*WW + gx];
        dout[((size_t)g*HH + gyA)*WW + gx] = dA + sA * (x1A - dA);
        dout[((size_t)g*HH + gyB)*WW + gx] = dB + sB * (x1B - dB);
    }
}

// ---------------------------------------------------------------------------
extern "C" void kernel_launch(void* const* d_in, const int* in_sizes, int n_in,
                              void* d_out, int out_size)
{
    const float* d1  = (const float*)d_in[0];
    const float* We  = (const float*)d_in[1];
    const float* Wp  = (const float*)d_in[2];
    const float* We2 = (const float*)d_in[3];
    const float* Wg  = (const float*)d_in[4];
    float* out = (float*)d_out;

    cudaFuncSetAttribute((const void*)k_stage_b,
                         cudaFuncAttributeMaxDynamicSharedMemorySize,
                         SMEM_B_BYTES);

    dim3 grid(WW/TX, HH/TYF, BB);
    const int HW = HH * WW;
    const int WSZ = CC*CC*9;
    const int GSZ = CC*2*9*2;

    k_stage_a<<<grid, NT>>>(d1, 0, We + 0*WSZ, Wp + 0*WSZ, out, 0);
    k_stage_b<<<grid, NT, SMEM_B_BYTES>>>(d1, 0, 0, out + 0*HW, We2 + 0*WSZ, Wg + 0*GSZ);

    k_stage_a<<<grid, NT>>>(nullptr, 0, We + 1*WSZ, Wp + 1*WSZ, out, 1);
    k_stage_b<<<grid, NT, SMEM_B_BYTES>>>(nullptr, 0, 1, out + 1*HW, We2 + 1*WSZ, Wg + 1*GSZ);

    k_stage_a<<<grid, NT>>>(nullptr, 1, We + 2*WSZ, Wp + 2*WSZ, out, 2);
    k_stage_b<<<grid, NT, SMEM_B_BYTES>>>(nullptr, 1, 0, out + 2*HW, We2 + 2*WSZ, Wg + 2*GSZ);

    k_stage_a<<<grid, NT>>>(nullptr, 0, We + 3*WSZ, Wp + 3*WSZ, out, 3);
}

// round 14
// speedup vs baseline: 2.6101x; 2.6101x over previous
#include <cuda_runtime.h>
#include <math.h>

#define CC 8
#define HH 256
#define WW 256
#define BB 8
#define NB 4
#define TX 32
#define TYF 16            // stage_b tile height
#define TYH 8
#define NT 256

// stage_a: 32x32 tile, 512 threads, 2 px/thread (rows ty, ty+16)
#define TYA 32
#define NTA 512

// scratch (no allocations allowed): f features + d1 ping-pong
__device__ float g_f[(size_t)BB*CC*HH*WW];
__device__ float g_d1[2][(size_t)BB*CC*HH*WW];

// ---------------------------------------------------------------------------
// Stage A: 32x32 tile, dynamic smem (83KB), paired 2px/thread (proven R10
// register shape: cap 128, no forced squeeze). 1 CTA x 16 warps per SM.
// ---------------------------------------------------------------------------
#define A_ND1  (CC*(TYA+4)*(TX+4))    // 8*36*36 = 10368
#define A_NF   (CC*(TYA+2)*(TX+2))    // 8*34*34 = 9248
#define SMEM_A_BYTES ((A_ND1 + A_NF + 2*CC*CC*9) * 4)   // 83,072

#define AD1(c,y,x) sa_d1[((c)*(TYA+4) + (y))*(TX+4) + (x)]
#define AF(c,y,x)  sa_f [((c)*(TYA+2) + (y))*(TX+2) + (x)]

__global__ __launch_bounds__(NTA, 1) void k_stage_a(
    const float* __restrict__ d1_ext, int src,
    const float* __restrict__ We, const float* __restrict__ Wp,
    float* __restrict__ out, int blk)
{
    extern __shared__ __align__(16) float smem[];
    float* sa_d1 = smem;                    // halo-2: 36x36 per channel
    float* sa_f  = sa_d1 + A_ND1;           // halo-1: 34x34 per channel
    float* s_We  = sa_f + A_NF;             // [c][k][o]
    float* s_Wp  = s_We + CC*CC*9;

    const int tid = threadIdx.x;
    const int b  = blockIdx.z;
    const int x0 = blockIdx.x * TX;
    const int y0 = blockIdx.y * TYA;

    const float* d1p = d1_ext ? d1_ext : &g_d1[src][0];
    const float* d1b = d1p + (size_t)b * CC * HH * WW;

    for (int i = tid; i < CC*CC*9; i += NTA) {
        int o = i / 72, r = i % 72, c = r / 9, k = r % 9;
        s_We[c*72 + k*8 + o] = We[i];
        s_Wp[c*72 + k*8 + o] = Wp[i];
    }

    // d1 tile halo-2 (zero pad)
    for (int i = tid; i < A_ND1; i += NTA) {
        int c  = i / ((TYA+4)*(TX+4));
        int r  = i % ((TYA+4)*(TX+4));
        int ly = r / (TX+4), lx = r % (TX+4);
        int gy = y0 + ly - 2, gx = x0 + lx - 2;
        float v = 0.f;
        if (gy >= 0 && gy < HH && gx >= 0 && gx < WW)
            v = d1b[((size_t)c*HH + gy)*WW + gx];
        sa_d1[i] = v;
    }
    __syncthreads();

    // f on halo-1 extended tile (34x34); zero outside image
    for (int i = tid; i < (TYA+2)*(TX+2); i += NTA) {
        int ly = i / (TX+2), lx = i % (TX+2);
        int gy = y0 + ly - 1, gx = x0 + lx - 1;
        float a0 = 0.f, a1 = 0.f, a2 = 0.f, a3 = 0.f;
        float a4 = 0.f, a5 = 0.f, a6 = 0.f, a7 = 0.f;
        if (gy >= 0 && gy < HH && gx >= 0 && gx < WW) {
            #pragma unroll
            for (int c = 0; c < CC; c++) {
                #pragma unroll
                for (int k = 0; k < 9; k++) {
                    float v = AD1(c, ly + k/3, lx + k%3);
                    float4 wa = *(const float4*)&s_We[c*72 + k*8];
                    float4 wb = *(const float4*)&s_We[c*72 + k*8 + 4];
                    a0 = fmaf(v, wa.x, a0); a1 = fmaf(v, wa.y, a1);
                    a2 = fmaf(v, wa.z, a2); a3 = fmaf(v, wa.w, a3);
                    a4 = fmaf(v, wb.x, a4); a5 = fmaf(v, wb.y, a5);
                    a6 = fmaf(v, wb.z, a6); a7 = fmaf(v, wb.w, a7);
                }
            }
        }
        AF(0, ly, lx) = a0; AF(1, ly, lx) = a1;
        AF(2, ly, lx) = a2; AF(3, ly, lx) = a3;
        AF(4, ly, lx) = a4; AF(5, ly, lx) = a5;
        AF(6, ly, lx) = a6; AF(7, ly, lx) = a7;
    }
    __syncthreads();

    // two core pixels per thread: rows tyA and tyA+16 (paired, proven shape)
    const int tyA = tid / TX, tx = tid % TX;
    const int tyB = tyA + (TYA/2);

    float fcA[CC], fcB[CC];
    #pragma unroll
    for (int c = 0; c < CC; c++) {
        fcA[c] = AF(c, tyA+1, tx+1);
        fcB[c] = AF(c, tyB+1, tx+1);
    }

    float aA[CC], aB[CC];
    #pragma unroll
    for (int o = 0; o < CC; o++) { aA[o] = 0.f; aB[o] = 0.f; }

    #pragma unroll
    for (int k = 0; k < 9; k++) {
        const int dy = k/3, dx = k%3;
        float pvA[CC], pvB[CC];
        float sA = 0.f, sB = 0.f;
        #pragma unroll
        for (int c = 0; c < CC; c++) {
            pvA[c] = AF(c, tyA+dy, tx+dx);
            pvB[c] = AF(c, tyB+dy, tx+dx);
            float dA = pvA[c] - fcA[c];
            float dB = pvB[c] - fcB[c];
            sA = fmaf(dA, dA, sA);
            sB = fmaf(dB, dB, sB);
        }
        float kA = __expf(-0.5f * sA);
        float kB = __expf(-0.5f * sB);
        #pragma unroll
        for (int c = 0; c < CC; c++) {
            float vA = pvA[c] * kA;
            float vB = pvB[c] * kB;
            float4 wa = *(const float4*)&s_Wp[c*72 + k*8];
            float4 wb = *(const float4*)&s_Wp[c*72 + k*8 + 4];
            aA[0] = fmaf(vA, wa.x, aA[0]); aB[0] = fmaf(vB, wa.x, aB[0]);
            aA[1] = fmaf(vA, wa.y, aA[1]); aB[1] = fmaf(vB, wa.y, aB[1]);
            aA[2] = fmaf(vA, wa.z, aA[2]); aB[2] = fmaf(vB, wa.z, aB[2]);
            aA[3] = fmaf(vA, wa.w, aA[3]); aB[3] = fmaf(vB, wa.w, aB[3]);
            aA[4] = fmaf(vA, wb.x, aA[4]); aB[4] = fmaf(vB, wb.x, aB[4]);
            aA[5] = fmaf(vA, wb.y, aA[5]); aB[5] = fmaf(vB, wb.y, aB[5]);
            aA[6] = fmaf(vA, wb.z, aA[6]); aB[6] = fmaf(vB, wb.z, aB[6]);
            aA[7] = fmaf(vA, wb.w, aA[7]); aB[7] = fmaf(vB, wb.w, aB[7]);
        }
    }

    const int gx = x0 + tx;
    float* fo = g_f + (size_t)b * CC * HH * WW;
    const bool writeF = (blk != NB-1);   // last block's f is never consumed

    {
        float w1[CC]; float m = -1e30f;
        #pragma unroll
        for (int c = 0; c < CC; c++) { w1[c] = aA[c]*fcA[c]*10.f; m = fmaxf(m, w1[c]); }
        float se = 0.f, sd = 0.f;
        #pragma unroll
        for (int c = 0; c < CC; c++) {
            float e = __expf(w1[c] - m);
            se += e;
            sd = fmaf(e, AD1(c, tyA+2, tx+2), sd);
        }
        const int gy = y0 + tyA;
        out[(((size_t)b*NB + blk)*HH + gy)*WW + gx] = sd / se;
        if (writeF) {
            #pragma unroll
            for (int c = 0; c < CC; c++)
                fo[((size_t)c*HH + gy)*WW + gx] = fcA[c];
        }
    }
    {
        float w1[CC]; float m = -1e30f;
        #pragma unroll
        for (int c = 0; c < CC; c++) { w1[c] = aB[c]*fcB[c]*10.f; m = fmaxf(m, w1[c]); }
        float se = 0.f, sd = 0.f;
        #pragma unroll
        for (int c = 0; c < CC; c++) {
            float e = __expf(w1[c] - m);
            se += e;
            sd = fmaf(e, AD1(c, tyB+2, tx+2), sd);
        }
        const int gy = y0 + tyB;
        out[(((size_t)b*NB + blk)*HH + gy)*WW + gx] = sd / se;
        if (writeF) {
            #pragma unroll
            for (int c = 0; c < CC; c++)
                fo[((size_t)c*HH + gy)*WW + gx] = fcB[c];
        }
    }
}

// ---------------------------------------------------------------------------
// Stage B (EXACT R10 winner): smem aliased to 48.96KB, 4 CTAs/SM, 64-reg cap.
// ---------------------------------------------------------------------------
#define NB_D1   (CC*(TYF+4)*(TX+4))   // 5760  (s_da; later aliased by s_f)
#define NB_X1   ((TYF+4)*(TX+4))      // 720
#define NB_F    (CC*(TYF+2)*(TX+2))   // 4896  (fits inside NB_D1 region)
#define SMEM_B_BYTES ((NB_D1 + NB_X1 + NB_F + 576 + 288) * 4)   // 48,960

#define SDA(c,y,x) s_da[((c)*(TYF+4) + (y))*(TX+4) + (x)]
#define SX1(y,x)   s_x1[(y)*(TX+4) + (x)]
#define SF(c,y,x)  s_f [((c)*(TYF+2) + (y))*(TX+2) + (x)]
#define SFX(c,y,x) s_fx[((c)*(TYF+2) + (y))*(TX+2) + (x)]

__global__ __launch_bounds__(NT, 4) void k_stage_b(
    const float* __restrict__ d1_ext, int src, int dst,
    const float* __restrict__ x1base,
    const float* __restrict__ We2, const float* __restrict__ Wg)
{
    extern __shared__ __align__(16) float smem[];
    float* s_da  = smem;                 // |d1 - x1| halo-2; dead after fx conv
    float* s_f   = smem;                 // ALIAS: f halo-1, loaded after fx conv
    float* s_x1  = s_da + NB_D1;
    float* s_fx  = s_x1 + NB_X1;
    float* s_We2 = s_fx + NB_F;
    float4* s_Wg4 = (float4*)(s_We2 + 576);

    const int tid = threadIdx.x;
    const int b  = blockIdx.z;
    const int x0 = blockIdx.x * TX;
    const int y0 = blockIdx.y * TYF;

    const float* d1p = d1_ext ? d1_ext : &g_d1[src][0];
    const float* d1b = d1p + (size_t)b * CC * HH * WW;
    const float* x1b = x1base + (size_t)b * NB * HH * WW;
    const float* fb  = g_f + (size_t)b * CC * HH * WW;

    // phase 0: weights + x1 halo-2
    for (int i = tid; i < CC*CC*9; i += NT) {
        int o = i / 72, r = i % 72, c = r / 9, k = r % 9;
        s_We2[c*72 + k*8 + o] = We2[i];
    }
    for (int i = tid; i < CC*9; i += NT) {
        int g = i / 9, k = i % 9;
        s_Wg4[i] = make_float4(Wg[(g*2+0)*18 + k], Wg[(g*2+0)*18 + 9 + k],
                               Wg[(g*2+1)*18 + k], Wg[(g*2+1)*18 + 9 + k]);
    }
    for (int i = tid; i < NB_X1; i += NT) {
        int ly = i / (TX+4), lx = i % (TX+4);
        int gy = y0 + ly - 2, gx = x0 + lx - 2;
        float v = 0.f;
        if (gy >= 0 && gy < HH && gx >= 0 && gx < WW)
            v = x1b[(size_t)gy*WW + gx];
        SX1(ly, lx) = v;
    }
    __syncthreads();

    // phase 1: s_da = |d1 - x1| (out-of-image |0-0|=0 matches zero-pad)
    for (int i = tid; i < NB_D1; i += NT) {
        int c  = i / ((TYF+4)*(TX+4));
        int r  = i % ((TYF+4)*(TX+4));
        int ly = r / (TX+4), lx = r % (TX+4);
        int gy = y0 + ly - 2, gx = x0 + lx - 2;
        float v = 0.f;
        if (gy >= 0 && gy < HH && gx >= 0 && gx < WW)
            v = fabsf(d1b[((size_t)c*HH + gy)*WW + gx] - s_x1[r]);
        s_da[i] = v;
    }
    __syncthreads();

    // phase 2: fx = conv(s_da, We2) on halo-1 extended tile -> s_fx
    for (int i = tid; i < (TYF+2)*(TX+2); i += NT) {
        int ly = i / (TX+2), lx = i % (TX+2);
        int gy = y0 + ly - 1, gx = x0 + lx - 1;
        float a0 = 0.f, a1 = 0.f, a2 = 0.f, a3 = 0.f;
        float a4 = 0.f, a5 = 0.f, a6 = 0.f, a7 = 0.f;
        if (gy >= 0 && gy < HH && gx >= 0 && gx < WW) {
            #pragma unroll
            for (int c = 0; c < CC; c++) {
                #pragma unroll
                for (int k = 0; k < 9; k++) {
                    float v = SDA(c, ly + k/3, lx + k%3);
                    float4 wa = *(const float4*)&s_We2[c*72 + k*8];
                    float4 wb = *(const float4*)&s_We2[c*72 + k*8 + 4];
                    a0 = fmaf(v, wa.x, a0); a1 = fmaf(v, wa.y, a1);
                    a2 = fmaf(v, wa.z, a2); a3 = fmaf(v, wa.w, a3);
                    a4 = fmaf(v, wb.x, a4); a5 = fmaf(v, wb.y, a5);
                    a6 = fmaf(v, wb.z, a6); a7 = fmaf(v, wb.w, a7);
                }
            }
        }
        SFX(0, ly, lx) = a0; SFX(1, ly, lx) = a1;
        SFX(2, ly, lx) = a2; SFX(3, ly, lx) = a3;
        SFX(4, ly, lx) = a4; SFX(5, ly, lx) = a5;
        SFX(6, ly, lx) = a6; SFX(7, ly, lx) = a7;
    }
    __syncthreads();   // s_da fully consumed

    // phase 2b: load f halo-1 into the aliased buffer
    for (int i = tid; i < NB_F; i += NT) {
        int c  = i / ((TYF+2)*(TX+2));
        int r  = i % ((TYF+2)*(TX+2));
        int ly = r / (TX+2), lx = r % (TX+2);
        int gy = y0 + ly - 1, gx = x0 + lx - 1;
        float v = 0.f;
        if (gy >= 0 && gy < HH && gx >= 0 && gx < WW)
            v = fb[((size_t)c*HH + gy)*WW + gx];
        s_f[i] = v;
    }
    __syncthreads();

    // phase 3: grouped paconv + blend; 2 core pixels/thread (split pairing)
    const int tyA = tid / TX, tx = tid % TX;
    const int tyB = tyA + TYH;
    const int gx = x0 + tx;
    const int gyA = y0 + tyA, gyB = y0 + tyB;
    const float x1A = SX1(tyA+2, tx+2);
    const float x1B = SX1(tyB+2, tx+2);
    float* dout = &g_d1[dst][0] + (size_t)b * CC * HH * WW;

    #pragma unroll
    for (int g = 0; g < CC; g++) {
        const float cfA  = SF (g, tyA+1, tx+1);
        const float cfxA = SFX(g, tyA+1, tx+1);
        const float cfB  = SF (g, tyB+1, tx+1);
        const float cfxB = SFX(g, tyB+1, tx+1);
        float w0A = 0.f, w1A = 0.f, w0B = 0.f, w1B = 0.f;
        #pragma unroll
        for (int k = 0; k < 9; k++) {
            const int dy = k/3, dx = k%3;
            float4 w = s_Wg4[g*9 + k];
            float pfA  = SF (g, tyA+dy, tx+dx);
            float pfxA = SFX(g, tyA+dy, tx+dx);
            float dfA = pfA - cfA, dfxA = pfxA - cfxA;
            float kernA = __expf(-0.5f * fmaf(dfA, dfA, dfxA*dfxA));
            w0A = fmaf(kernA, fmaf(pfA, w.x, pfxA * w.y), w0A);
            w1A = fmaf(kernA, fmaf(pfA, w.z, pfxA * w.w), w1A);

            float pfB  = SF (g, tyB+dy, tx+dx);
            float pfxB = SFX(g, tyB+dy, tx+dx);
            float dfB = pfB - cfB, dfxB = pfxB - cfxB;
            float kernB = __expf(-0.5f * fmaf(dfB, dfB, dfxB*dfxB));
            w0B = fmaf(kernB, fmaf(pfB, w.x, pfxB * w.y), w0B);
            w1B = fmaf(kernB, fmaf(pfB, w.z, pfxB * w.w), w1B);
        }
        float sA = 1.f / (1.f + __expf(-2.0f * (w1A - w0A)));
        float sB = 1.f / (1.f + __expf(-2.0f * (w1B - w0B)));
        // original d1 centers from global (smem holds f, not d1)
        float dA = d1b[((size_t)g*HH + gyA)*WW + gx];
        float dB = d1b[((size_t)g*HH + gyB)*WW + gx];
        dout[((size_t)g*HH + gyA)*WW + gx] = dA + sA * (x1A - dA);
        dout[((size_t)g*HH + gyB)*WW + gx] = dB + sB * (x1B - dB);
    }
}

// ---------------------------------------------------------------------------
extern "C" void kernel_launch(void* const* d_in, const int* in_sizes, int n_in,
                              void* d_out, int out_size)
{
    const float* d1  = (const float*)d_in[0];
    const float* We  = (const float*)d_in[1];
    const float* Wp  = (const float*)d_in[2];
    const float* We2 = (const float*)d_in[3];
    const float* Wg  = (const float*)d_in[4];
    float* out = (float*)d_out;

    cudaFuncSetAttribute((const void*)k_stage_a,
                         cudaFuncAttributeMaxDynamicSharedMemorySize,
                         SMEM_A_BYTES);
    cudaFuncSetAttribute((const void*)k_stage_b,
                         cudaFuncAttributeMaxDynamicSharedMemorySize,
                         SMEM_B_BYTES);

    dim3 gridA(WW/TX, HH/TYA, BB);   // (8, 8, 8)
    dim3 gridB(WW/TX, HH/TYF, BB);   // (8, 16, 8)
    const int HW = HH * WW;
    const int WSZ = CC*CC*9;
    const int GSZ = CC*2*9*2;

    k_stage_a<<<gridA, NTA, SMEM_A_BYTES>>>(d1, 0, We + 0*WSZ, Wp + 0*WSZ, out, 0);
    k_stage_b<<<gridB, NT, SMEM_B_BYTES>>>(d1, 0, 0, out + 0*HW, We2 + 0*WSZ, Wg + 0*GSZ);

    k_stage_a<<<gridA, NTA, SMEM_A_BYTES>>>(nullptr, 0, We + 1*WSZ, Wp + 1*WSZ, out, 1);
    k_stage_b<<<gridB, NT, SMEM_B_BYTES>>>(nullptr, 0, 1, out + 1*HW, We2 + 1*WSZ, Wg + 1*GSZ);

    k_stage_a<<<gridA, NTA, SMEM_A_BYTES>>>(nullptr, 1, We + 2*WSZ, Wp + 2*WSZ, out, 2);
    k_stage_b<<<gridB, NT, SMEM_B_BYTES>>>(nullptr, 1, 0, out + 2*HW, We2 + 2*WSZ, Wg + 2*GSZ);

    k_stage_a<<<gridA, NTA, SMEM_A_BYTES>>>(nullptr, 0, We + 3*WSZ, Wp + 3*WSZ, out, 3);
}

// round 15
// speedup vs baseline: 2.7286x; 1.0454x over previous
#include <cuda_runtime.h>
#include <math.h>

#define CC 8
#define HH 256
#define WW 256
#define BB 8
#define NB 4
#define TX 32
#define TYF 16            // tile height (2 core pixels per thread)
#define TYH 8             // vertical split
#define NT 256

// scratch (no allocations allowed): f features + d1 ping-pong
__device__ float g_f[(size_t)BB*CC*HH*WW];
__device__ float g_d1[2][(size_t)BB*CC*HH*WW];

// ---------------------------------------------------------------------------
// Stage A (exact R10 shape): f = conv(d1, We); w1 = paconv(f, Wp) * f;
// x1 = softargmax(d1, w1). Paired 2 pixels/thread, (256,2), static smem.
// Only change vs R10: g_f writes skipped on the last block (never consumed).
// ---------------------------------------------------------------------------
__global__ __launch_bounds__(NT, 2) void k_stage_a(
    const float* __restrict__ d1_ext, int src,
    const float* __restrict__ We, const float* __restrict__ Wp,
    float* __restrict__ out, int blk)
{
    __shared__ float s_d1[CC][TYF+4][TX+4];   // halo 2
    __shared__ float s_f [CC][TYF+2][TX+2];   // halo 1
    __shared__ __align__(16) float s_We[CC*9*CC];   // [c][k][o]
    __shared__ __align__(16) float s_Wp[CC*9*CC];   // [c][k][o]

    const int tid = threadIdx.x;
    const int b  = blockIdx.z;
    const int x0 = blockIdx.x * TX;
    const int y0 = blockIdx.y * TYF;

    const float* d1p = d1_ext ? d1_ext : &g_d1[src][0];
    const float* d1b = d1p + (size_t)b * CC * HH * WW;

    for (int i = tid; i < CC*CC*9; i += NT) {
        int o = i / 72, r = i % 72, c = r / 9, k = r % 9;
        s_We[c*72 + k*8 + o] = We[i];
        s_Wp[c*72 + k*8 + o] = Wp[i];
    }

    for (int i = tid; i < CC*(TYF+4)*(TX+4); i += NT) {
        int c  = i / ((TYF+4)*(TX+4));
        int r  = i % ((TYF+4)*(TX+4));
        int ly = r / (TX+4), lx = r % (TX+4);
        int gy = y0 + ly - 2, gx = x0 + lx - 2;
        float v = 0.f;
        if (gy >= 0 && gy < HH && gx >= 0 && gx < WW)
            v = d1b[((size_t)c*HH + gy)*WW + gx];
        s_d1[c][ly][lx] = v;
    }
    __syncthreads();

    for (int i = tid; i < (TYF+2)*(TX+2); i += NT) {
        int ly = i / (TX+2), lx = i % (TX+2);
        int gy = y0 + ly - 1, gx = x0 + lx - 1;
        float a0 = 0.f, a1 = 0.f, a2 = 0.f, a3 = 0.f;
        float a4 = 0.f, a5 = 0.f, a6 = 0.f, a7 = 0.f;
        if (gy >= 0 && gy < HH && gx >= 0 && gx < WW) {
            #pragma unroll
            for (int c = 0; c < CC; c++) {
                #pragma unroll
                for (int k = 0; k < 9; k++) {
                    float v = s_d1[c][ly + k/3][lx + k%3];
                    float4 wa = *(const float4*)&s_We[c*72 + k*8];
                    float4 wb = *(const float4*)&s_We[c*72 + k*8 + 4];
                    a0 = fmaf(v, wa.x, a0); a1 = fmaf(v, wa.y, a1);
                    a2 = fmaf(v, wa.z, a2); a3 = fmaf(v, wa.w, a3);
                    a4 = fmaf(v, wb.x, a4); a5 = fmaf(v, wb.y, a5);
                    a6 = fmaf(v, wb.z, a6); a7 = fmaf(v, wb.w, a7);
                }
            }
        }
        s_f[0][ly][lx] = a0; s_f[1][ly][lx] = a1;
        s_f[2][ly][lx] = a2; s_f[3][ly][lx] = a3;
        s_f[4][ly][lx] = a4; s_f[5][ly][lx] = a5;
        s_f[6][ly][lx] = a6; s_f[7][ly][lx] = a7;
    }
    __syncthreads();

    const int tyA = tid / TX, tx = tid % TX;
    const int tyB = tyA + TYH;

    float fcA[CC], fcB[CC];
    #pragma unroll
    for (int c = 0; c < CC; c++) {
        fcA[c] = s_f[c][tyA+1][tx+1];
        fcB[c] = s_f[c][tyB+1][tx+1];
    }

    float aA[CC], aB[CC];
    #pragma unroll
    for (int o = 0; o < CC; o++) { aA[o] = 0.f; aB[o] = 0.f; }

    #pragma unroll
    for (int k = 0; k < 9; k++) {
        const int dy = k/3, dx = k%3;
        float pvA[CC], pvB[CC];
        float sA = 0.f, sB = 0.f;
        #pragma unroll
        for (int c = 0; c < CC; c++) {
            pvA[c] = s_f[c][tyA+dy][tx+dx];
            pvB[c] = s_f[c][tyB+dy][tx+dx];
            float dA = pvA[c] - fcA[c];
            float dB = pvB[c] - fcB[c];
            sA = fmaf(dA, dA, sA);
            sB = fmaf(dB, dB, sB);
        }
        float kA = __expf(-0.5f * sA);
        float kB = __expf(-0.5f * sB);
        #pragma unroll
        for (int c = 0; c < CC; c++) {
            float vA = pvA[c] * kA;
            float vB = pvB[c] * kB;
            float4 wa = *(const float4*)&s_Wp[c*72 + k*8];
            float4 wb = *(const float4*)&s_Wp[c*72 + k*8 + 4];
            aA[0] = fmaf(vA, wa.x, aA[0]); aB[0] = fmaf(vB, wa.x, aB[0]);
            aA[1] = fmaf(vA, wa.y, aA[1]); aB[1] = fmaf(vB, wa.y, aB[1]);
            aA[2] = fmaf(vA, wa.z, aA[2]); aB[2] = fmaf(vB, wa.z, aB[2]);
            aA[3] = fmaf(vA, wa.w, aA[3]); aB[3] = fmaf(vB, wa.w, aB[3]);
            aA[4] = fmaf(vA, wb.x, aA[4]); aB[4] = fmaf(vB, wb.x, aB[4]);
            aA[5] = fmaf(vA, wb.y, aA[5]); aB[5] = fmaf(vB, wb.y, aB[5]);
            aA[6] = fmaf(vA, wb.z, aA[6]); aB[6] = fmaf(vB, wb.z, aB[6]);
            aA[7] = fmaf(vA, wb.w, aA[7]); aB[7] = fmaf(vB, wb.w, aB[7]);
        }
    }

    const int gx = x0 + tx;
    float* fo = g_f + (size_t)b * CC * HH * WW;
    const bool writeF = (blk != NB-1);   // last block's f is never consumed

    {
        float w1[CC]; float m = -1e30f;
        #pragma unroll
        for (int c = 0; c < CC; c++) { w1[c] = aA[c]*fcA[c]*10.f; m = fmaxf(m, w1[c]); }
        float se = 0.f, sd = 0.f;
        #pragma unroll
        for (int c = 0; c < CC; c++) {
            float e = __expf(w1[c] - m);
            se += e;
            sd = fmaf(e, s_d1[c][tyA+2][tx+2], sd);
        }
        const int gy = y0 + tyA;
        out[(((size_t)b*NB + blk)*HH + gy)*WW + gx] = sd / se;
        if (writeF) {
            #pragma unroll
            for (int c = 0; c < CC; c++)
                fo[((size_t)c*HH + gy)*WW + gx] = fcA[c];
        }
    }
    {
        float w1[CC]; float m = -1e30f;
        #pragma unroll
        for (int c = 0; c < CC; c++) { w1[c] = aB[c]*fcB[c]*10.f; m = fmaxf(m, w1[c]); }
        float se = 0.f, sd = 0.f;
        #pragma unroll
        for (int c = 0; c < CC; c++) {
            float e = __expf(w1[c] - m);
            se += e;
            sd = fmaf(e, s_d1[c][tyB+2][tx+2], sd);
        }
        const int gy = y0 + tyB;
        out[(((size_t)b*NB + blk)*HH + gy)*WW + gx] = sd / se;
        if (writeF) {
            #pragma unroll
            for (int c = 0; c < CC; c++)
                fo[((size_t)c*HH + gy)*WW + gx] = fcB[c];
        }
    }
}

// ---------------------------------------------------------------------------
// Stage B (EXACT R10 winner): smem aliased to 48.96KB, 4 CTAs/SM, 64-reg cap.
// ---------------------------------------------------------------------------
#define NB_D1   (CC*(TYF+4)*(TX+4))   // 5760  (s_da; later aliased by s_f)
#define NB_X1   ((TYF+4)*(TX+4))      // 720
#define NB_F    (CC*(TYF+2)*(TX+2))   // 4896  (fits inside NB_D1 region)
#define SMEM_B_BYTES ((NB_D1 + NB_X1 + NB_F + 576 + 288) * 4)   // 48,960

#define SDA(c,y,x) s_da[((c)*(TYF+4) + (y))*(TX+4) + (x)]
#define SX1(y,x)   s_x1[(y)*(TX+4) + (x)]
#define SF(c,y,x)  s_f [((c)*(TYF+2) + (y))*(TX+2) + (x)]
#define SFX(c,y,x) s_fx[((c)*(TYF+2) + (y))*(TX+2) + (x)]

__global__ __launch_bounds__(NT, 4) void k_stage_b(
    const float* __restrict__ d1_ext, int src, int dst,
    const float* __restrict__ x1base,
    const float* __restrict__ We2, const float* __restrict__ Wg)
{
    extern __shared__ __align__(16) float smem[];
    float* s_da  = smem;                 // |d1 - x1| halo-2; dead after fx conv
    float* s_f   = smem;                 // ALIAS: f halo-1, loaded after fx conv
    float* s_x1  = s_da + NB_D1;
    float* s_fx  = s_x1 + NB_X1;
    float* s_We2 = s_fx + NB_F;
    float4* s_Wg4 = (float4*)(s_We2 + 576);

    const int tid = threadIdx.x;
    const int b  = blockIdx.z;
    const int x0 = blockIdx.x * TX;
    const int y0 = blockIdx.y * TYF;

    const float* d1p = d1_ext ? d1_ext : &g_d1[src][0];
    const float* d1b = d1p + (size_t)b * CC * HH * WW;
    const float* x1b = x1base + (size_t)b * NB * HH * WW;
    const float* fb  = g_f + (size_t)b * CC * HH * WW;

    // phase 0: weights + x1 halo-2
    for (int i = tid; i < CC*CC*9; i += NT) {
        int o = i / 72, r = i % 72, c = r / 9, k = r % 9;
        s_We2[c*72 + k*8 + o] = We2[i];
    }
    for (int i = tid; i < CC*9; i += NT) {
        int g = i / 9, k = i % 9;
        s_Wg4[i] = make_float4(Wg[(g*2+0)*18 + k], Wg[(g*2+0)*18 + 9 + k],
                               Wg[(g*2+1)*18 + k], Wg[(g*2+1)*18 + 9 + k]);
    }
    for (int i = tid; i < NB_X1; i += NT) {
        int ly = i / (TX+4), lx = i % (TX+4);
        int gy = y0 + ly - 2, gx = x0 + lx - 2;
        float v = 0.f;
        if (gy >= 0 && gy < HH && gx >= 0 && gx < WW)
            v = x1b[(size_t)gy*WW + gx];
        SX1(ly, lx) = v;
    }
    __syncthreads();

    // phase 1: s_da = |d1 - x1| (out-of-image |0-0|=0 matches zero-pad)
    for (int i = tid; i < NB_D1; i += NT) {
        int c  = i / ((TYF+4)*(TX+4));
        int r  = i % ((TYF+4)*(TX+4));
        int ly = r / (TX+4), lx = r % (TX+4);
        int gy = y0 + ly - 2, gx = x0 + lx - 2;
        float v = 0.f;
        if (gy >= 0 && gy < HH && gx >= 0 && gx < WW)
            v = fabsf(d1b[((size_t)c*HH + gy)*WW + gx] - s_x1[r]);
        s_da[i] = v;
    }
    __syncthreads();

    // phase 2: fx = conv(s_da, We2) on halo-1 extended tile -> s_fx
    for (int i = tid; i < (TYF+2)*(TX+2); i += NT) {
        int ly = i / (TX+2), lx = i % (TX+2);
        int gy = y0 + ly - 1, gx = x0 + lx - 1;
        float a0 = 0.f, a1 = 0.f, a2 = 0.f, a3 = 0.f;
        float a4 = 0.f, a5 = 0.f, a6 = 0.f, a7 = 0.f;
        if (gy >= 0 && gy < HH && gx >= 0 && gx < WW) {
            #pragma unroll
            for (int c = 0; c < CC; c++) {
                #pragma unroll
                for (int k = 0; k < 9; k++) {
                    float v = SDA(c, ly + k/3, lx + k%3);
                    float4 wa = *(const float4*)&s_We2[c*72 + k*8];
                    float4 wb = *(const float4*)&s_We2[c*72 + k*8 + 4];
                    a0 = fmaf(v, wa.x, a0); a1 = fmaf(v, wa.y, a1);
                    a2 = fmaf(v, wa.z, a2); a3 = fmaf(v, wa.w, a3);
                    a4 = fmaf(v, wb.x, a4); a5 = fmaf(v, wb.y, a5);
                    a6 = fmaf(v, wb.z, a6); a7 = fmaf(v, wb.w, a7);
                }
            }
        }
        SFX(0, ly, lx) = a0; SFX(1, ly, lx) = a1;
        SFX(2, ly, lx) = a2; SFX(3, ly, lx) = a3;
        SFX(4, ly, lx) = a4; SFX(5, ly, lx) = a5;
        SFX(6, ly, lx) = a6; SFX(7, ly, lx) = a7;
    }
    __syncthreads();   // s_da fully consumed

    // phase 2b: load f halo-1 into the aliased buffer
    for (int i = tid; i < NB_F; i += NT) {
        int c  = i / ((TYF+2)*(TX+2));
        int r  = i % ((TYF+2)*(TX+2));
        int ly = r / (TX+2), lx = r % (TX+2);
        int gy = y0 + ly - 1, gx = x0 + lx - 1;
        float v = 0.f;
        if (gy >= 0 && gy < HH && gx >= 0 && gx < WW)
            v = fb[((size_t)c*HH + gy)*WW + gx];
        s_f[i] = v;
    }
    __syncthreads();

    // phase 3: grouped paconv + blend; 2 core pixels/thread (split pairing)
    const int tyA = tid / TX, tx = tid % TX;
    const int tyB = tyA + TYH;
    const int gx = x0 + tx;
    const int gyA = y0 + tyA, gyB = y0 + tyB;
    const float x1A = SX1(tyA+2, tx+2);
    const float x1B = SX1(tyB+2, tx+2);
    float* dout = &g_d1[dst][0] + (size_t)b * CC * HH * WW;

    #pragma unroll
    for (int g = 0; g < CC; g++) {
        const float cfA  = SF (g, tyA+1, tx+1);
        const float cfxA = SFX(g, tyA+1, tx+1);
        const float cfB  = SF (g, tyB+1, tx+1);
        const float cfxB = SFX(g, tyB+1, tx+1);
        float w0A = 0.f, w1A = 0.f, w0B = 0.f, w1B = 0.f;
        #pragma unroll
        for (int k = 0; k < 9; k++) {
            const int dy = k/3, dx = k%3;
            float4 w = s_Wg4[g*9 + k];
            float pfA  = SF (g, tyA+dy, tx+dx);
            float pfxA = SFX(g, tyA+dy, tx+dx);
            float dfA = pfA - cfA, dfxA = pfxA - cfxA;
            float kernA = __expf(-0.5f * fmaf(dfA, dfA, dfxA*dfxA));
            w0A = fmaf(kernA, fmaf(pfA, w.x, pfxA * w.y), w0A);
            w1A = fmaf(kernA, fmaf(pfA, w.z, pfxA * w.w), w1A);

            float pfB  = SF (g, tyB+dy, tx+dx);
            float pfxB = SFX(g, tyB+dy, tx+dx);
            float dfB = pfB - cfB, dfxB = pfxB - cfxB;
            float kernB = __expf(-0.5f * fmaf(dfB, dfB, dfxB*dfxB));
            w0B = fmaf(kernB, fmaf(pfB, w.x, pfxB * w.y), w0B);
            w1B = fmaf(kernB, fmaf(pfB, w.z, pfxB * w.w), w1B);
        }
        float sA = 1.f / (1.f + __expf(-2.0f * (w1A - w0A)));
        float sB = 1.f / (1.f + __expf(-2.0f * (w1B - w0B)));
        // original d1 centers from global (smem holds f, not d1)
        float dA = d1b[((size_t)g*HH + gyA)*WW + gx];
        float dB = d1b[((size_t)g*HH + gyB)*WW + gx];
        dout[((size_t)g*HH + gyA)*WW + gx] = dA + sA * (x1A - dA);
        dout[((size_t)g*HH + gyB)*WW + gx] = dB + sB * (x1B - dB);
    }
}

// ---------------------------------------------------------------------------
extern "C" void kernel_launch(void* const* d_in, const int* in_sizes, int n_in,
                              void* d_out, int out_size)
{
    const float* d1  = (const float*)d_in[0];
    const float* We  = (const float*)d_in[1];
    const float* Wp  = (const float*)d_in[2];
    const float* We2 = (const float*)d_in[3];
    const float* Wg  = (const float*)d_in[4];
    float* out = (float*)d_out;

    cudaFuncSetAttribute((const void*)k_stage_b,
                         cudaFuncAttributeMaxDynamicSharedMemorySize,
                         SMEM_B_BYTES);

    dim3 grid(WW/TX, HH/TYF, BB);
    const int HW = HH * WW;
    const int WSZ = CC*CC*9;
    const int GSZ = CC*2*9*2;

    k_stage_a<<<grid, NT>>>(d1, 0, We + 0*WSZ, Wp + 0*WSZ, out, 0);
    k_stage_b<<<grid, NT, SMEM_B_BYTES>>>(d1, 0, 0, out + 0*HW, We2 + 0*WSZ, Wg + 0*GSZ);

    k_stage_a<<<grid, NT>>>(nullptr, 0, We + 1*WSZ, Wp + 1*WSZ, out, 1);
    k_stage_b<<<grid, NT, SMEM_B_BYTES>>>(nullptr, 0, 1, out + 1*HW, We2 + 1*WSZ, Wg + 1*GSZ);

    k_stage_a<<<grid, NT>>>(nullptr, 1, We + 2*WSZ, Wp + 2*WSZ, out, 2);
    k_stage_b<<<grid, NT, SMEM_B_BYTES>>>(nullptr, 1, 0, out + 2*HW, We2 + 2*WSZ, Wg + 2*GSZ);

    k_stage_a<<<grid, NT>>>(nullptr, 0, We + 3*WSZ, Wp + 3*WSZ, out, 3);
}

// round 16
// speedup vs baseline: 2.7490x; 1.0075x over previous
#include <cuda_runtime.h>
#include <math.h>

#define CC 8
#define HH 256
#define WW 256
#define BB 8
#define NB 4
#define TX 32
#define TYF 16            // tile height (2 core pixels per thread)
#define TYH 8             // vertical split
#define NT 256

// scratch (no allocations allowed): f features + d1 ping-pong
__device__ float g_f[(size_t)BB*CC*HH*WW];
__device__ float g_d1[2][(size_t)BB*CC*HH*WW];

// ---------------------------------------------------------------------------
// Stage A (EXACT best-known shape): paired 2 pixels/thread, (256,2), static
// smem; g_f writes skipped on the last block.
// ---------------------------------------------------------------------------
__global__ __launch_bounds__(NT, 2) void k_stage_a(
    const float* __restrict__ d1_ext, int src,
    const float* __restrict__ We, const float* __restrict__ Wp,
    float* __restrict__ out, int blk)
{
    __shared__ float s_d1[CC][TYF+4][TX+4];   // halo 2
    __shared__ float s_f [CC][TYF+2][TX+2];   // halo 1
    __shared__ __align__(16) float s_We[CC*9*CC];   // [c][k][o]
    __shared__ __align__(16) float s_Wp[CC*9*CC];   // [c][k][o]

    const int tid = threadIdx.x;
    const int b  = blockIdx.z;
    const int x0 = blockIdx.x * TX;
    const int y0 = blockIdx.y * TYF;

    const float* d1p = d1_ext ? d1_ext : &g_d1[src][0];
    const float* d1b = d1p + (size_t)b * CC * HH * WW;

    for (int i = tid; i < CC*CC*9; i += NT) {
        int o = i / 72, r = i % 72, c = r / 9, k = r % 9;
        s_We[c*72 + k*8 + o] = We[i];
        s_Wp[c*72 + k*8 + o] = Wp[i];
    }

    for (int i = tid; i < CC*(TYF+4)*(TX+4); i += NT) {
        int c  = i / ((TYF+4)*(TX+4));
        int r  = i % ((TYF+4)*(TX+4));
        int ly = r / (TX+4), lx = r % (TX+4);
        int gy = y0 + ly - 2, gx = x0 + lx - 2;
        float v = 0.f;
        if (gy >= 0 && gy < HH && gx >= 0 && gx < WW)
            v = d1b[((size_t)c*HH + gy)*WW + gx];
        s_d1[c][ly][lx] = v;
    }
    __syncthreads();

    for (int i = tid; i < (TYF+2)*(TX+2); i += NT) {
        int ly = i / (TX+2), lx = i % (TX+2);
        int gy = y0 + ly - 1, gx = x0 + lx - 1;
        float a0 = 0.f, a1 = 0.f, a2 = 0.f, a3 = 0.f;
        float a4 = 0.f, a5 = 0.f, a6 = 0.f, a7 = 0.f;
        if (gy >= 0 && gy < HH && gx >= 0 && gx < WW) {
            #pragma unroll
            for (int c = 0; c < CC; c++) {
                #pragma unroll
                for (int k = 0; k < 9; k++) {
                    float v = s_d1[c][ly + k/3][lx + k%3];
                    float4 wa = *(const float4*)&s_We[c*72 + k*8];
                    float4 wb = *(const float4*)&s_We[c*72 + k*8 + 4];
                    a0 = fmaf(v, wa.x, a0); a1 = fmaf(v, wa.y, a1);
                    a2 = fmaf(v, wa.z, a2); a3 = fmaf(v, wa.w, a3);
                    a4 = fmaf(v, wb.x, a4); a5 = fmaf(v, wb.y, a5);
                    a6 = fmaf(v, wb.z, a6); a7 = fmaf(v, wb.w, a7);
                }
            }
        }
        s_f[0][ly][lx] = a0; s_f[1][ly][lx] = a1;
        s_f[2][ly][lx] = a2; s_f[3][ly][lx] = a3;
        s_f[4][ly][lx] = a4; s_f[5][ly][lx] = a5;
        s_f[6][ly][lx] = a6; s_f[7][ly][lx] = a7;
    }
    __syncthreads();

    const int tyA = tid / TX, tx = tid % TX;
    const int tyB = tyA + TYH;

    float fcA[CC], fcB[CC];
    #pragma unroll
    for (int c = 0; c < CC; c++) {
        fcA[c] = s_f[c][tyA+1][tx+1];
        fcB[c] = s_f[c][tyB+1][tx+1];
    }

    float aA[CC], aB[CC];
    #pragma unroll
    for (int o = 0; o < CC; o++) { aA[o] = 0.f; aB[o] = 0.f; }

    #pragma unroll
    for (int k = 0; k < 9; k++) {
        const int dy = k/3, dx = k%3;
        float pvA[CC], pvB[CC];
        float sA = 0.f, sB = 0.f;
        #pragma unroll
        for (int c = 0; c < CC; c++) {
            pvA[c] = s_f[c][tyA+dy][tx+dx];
            pvB[c] = s_f[c][tyB+dy][tx+dx];
            float dA = pvA[c] - fcA[c];
            float dB = pvB[c] - fcB[c];
            sA = fmaf(dA, dA, sA);
            sB = fmaf(dB, dB, sB);
        }
        float kA = __expf(-0.5f * sA);
        float kB = __expf(-0.5f * sB);
        #pragma unroll
        for (int c = 0; c < CC; c++) {
            float vA = pvA[c] * kA;
            float vB = pvB[c] * kB;
            float4 wa = *(const float4*)&s_Wp[c*72 + k*8];
            float4 wb = *(const float4*)&s_Wp[c*72 + k*8 + 4];
            aA[0] = fmaf(vA, wa.x, aA[0]); aB[0] = fmaf(vB, wa.x, aB[0]);
            aA[1] = fmaf(vA, wa.y, aA[1]); aB[1] = fmaf(vB, wa.y, aB[1]);
            aA[2] = fmaf(vA, wa.z, aA[2]); aB[2] = fmaf(vB, wa.z, aB[2]);
            aA[3] = fmaf(vA, wa.w, aA[3]); aB[3] = fmaf(vB, wa.w, aB[3]);
            aA[4] = fmaf(vA, wb.x, aA[4]); aB[4] = fmaf(vB, wb.x, aB[4]);
            aA[5] = fmaf(vA, wb.y, aA[5]); aB[5] = fmaf(vB, wb.y, aB[5]);
            aA[6] = fmaf(vA, wb.z, aA[6]); aB[6] = fmaf(vB, wb.z, aB[6]);
            aA[7] = fmaf(vA, wb.w, aA[7]); aB[7] = fmaf(vB, wb.w, aB[7]);
        }
    }

    const int gx = x0 + tx;
    float* fo = g_f + (size_t)b * CC * HH * WW;
    const bool writeF = (blk != NB-1);

    {
        float w1[CC]; float m = -1e30f;
        #pragma unroll
        for (int c = 0; c < CC; c++) { w1[c] = aA[c]*fcA[c]*10.f; m = fmaxf(m, w1[c]); }
        float se = 0.f, sd = 0.f;
        #pragma unroll
        for (int c = 0; c < CC; c++) {
            float e = __expf(w1[c] - m);
            se += e;
            sd = fmaf(e, s_d1[c][tyA+2][tx+2], sd);
        }
        const int gy = y0 + tyA;
        out[(((size_t)b*NB + blk)*HH + gy)*WW + gx] = sd / se;
        if (writeF) {
            #pragma unroll
            for (int c = 0; c < CC; c++)
                fo[((size_t)c*HH + gy)*WW + gx] = fcA[c];
        }
    }
    {
        float w1[CC]; float m = -1e30f;
        #pragma unroll
        for (int c = 0; c < CC; c++) { w1[c] = aB[c]*fcB[c]*10.f; m = fmaxf(m, w1[c]); }
        float se = 0.f, sd = 0.f;
        #pragma unroll
        for (int c = 0; c < CC; c++) {
            float e = __expf(w1[c] - m);
            se += e;
            sd = fmaf(e, s_d1[c][tyB+2][tx+2], sd);
        }
        const int gy = y0 + tyB;
        out[(((size_t)b*NB + blk)*HH + gy)*WW + gx] = sd / se;
        if (writeF) {
            #pragma unroll
            for (int c = 0; c < CC; c++)
                fo[((size_t)c*HH + gy)*WW + gx] = fcB[c];
        }
    }
}

// ---------------------------------------------------------------------------
// Stage B: R10 structure + explicit MLP-4 batching in global-load phases
// (1 and 2b). smem 48.96KB, 4 CTAs/SM, 64-reg cap.
// ---------------------------------------------------------------------------
#define NB_D1   (CC*(TYF+4)*(TX+4))   // 5760
#define NB_X1   ((TYF+4)*(TX+4))      // 720
#define NB_F    (CC*(TYF+2)*(TX+2))   // 4896
#define SMEM_B_BYTES ((NB_D1 + NB_X1 + NB_F + 576 + 288) * 4)   // 48,960

#define SDA(c,y,x) s_da[((c)*(TYF+4) + (y))*(TX+4) + (x)]
#define SX1(y,x)   s_x1[(y)*(TX+4) + (x)]
#define SF(c,y,x)  s_f [((c)*(TYF+2) + (y))*(TX+2) + (x)]
#define SFX(c,y,x) s_fx[((c)*(TYF+2) + (y))*(TX+2) + (x)]

__global__ __launch_bounds__(NT, 4) void k_stage_b(
    const float* __restrict__ d1_ext, int src, int dst,
    const float* __restrict__ x1base,
    const float* __restrict__ We2, const float* __restrict__ Wg)
{
    extern __shared__ __align__(16) float smem[];
    float* s_da  = smem;                 // |d1 - x1| halo-2; dead after fx conv
    float* s_f   = smem;                 // ALIAS: f halo-1, loaded after fx conv
    float* s_x1  = s_da + NB_D1;
    float* s_fx  = s_x1 + NB_X1;
    float* s_We2 = s_fx + NB_F;
    float4* s_Wg4 = (float4*)(s_We2 + 576);

    const int tid = threadIdx.x;
    const int b  = blockIdx.z;
    const int x0 = blockIdx.x * TX;
    const int y0 = blockIdx.y * TYF;

    const float* d1p = d1_ext ? d1_ext : &g_d1[src][0];
    const float* d1b = d1p + (size_t)b * CC * HH * WW;
    const float* x1b = x1base + (size_t)b * NB * HH * WW;
    const float* fb  = g_f + (size_t)b * CC * HH * WW;

    // phase 0: weights + x1 halo-2
    for (int i = tid; i < CC*CC*9; i += NT) {
        int o = i / 72, r = i % 72, c = r / 9, k = r % 9;
        s_We2[c*72 + k*8 + o] = We2[i];
    }
    for (int i = tid; i < CC*9; i += NT) {
        int g = i / 9, k = i % 9;
        s_Wg4[i] = make_float4(Wg[(g*2+0)*18 + k], Wg[(g*2+0)*18 + 9 + k],
                               Wg[(g*2+1)*18 + k], Wg[(g*2+1)*18 + 9 + k]);
    }
    for (int i = tid; i < NB_X1; i += NT) {
        int ly = i / (TX+4), lx = i % (TX+4);
        int gy = y0 + ly - 2, gx = x0 + lx - 2;
        float v = 0.f;
        if (gy >= 0 && gy < HH && gx >= 0 && gx < WW)
            v = x1b[(size_t)gy*WW + gx];
        SX1(ly, lx) = v;
    }
    __syncthreads();

    // phase 1: s_da = |d1 - x1|, MLP-4 batched loads
    #pragma unroll 1
    for (int base = tid; base < NB_D1; base += NT*4) {
        float v[4];
        #pragma unroll
        for (int u = 0; u < 4; u++) {
            int i = base + u*NT;
            v[u] = 0.f;
            if (i < NB_D1) {
                int c  = i / ((TYF+4)*(TX+4));
                int r  = i % ((TYF+4)*(TX+4));
                int ly = r / (TX+4), lx = r % (TX+4);
                int gy = y0 + ly - 2, gx = x0 + lx - 2;
                if (gy >= 0 && gy < HH && gx >= 0 && gx < WW)
                    v[u] = d1b[((size_t)c*HH + gy)*WW + gx];
            }
        }
        #pragma unroll
        for (int u = 0; u < 4; u++) {
            int i = base + u*NT;
            if (i < NB_D1)
                s_da[i] = fabsf(v[u] - s_x1[i % ((TYF+4)*(TX+4))]);
        }
    }
    __syncthreads();

    // phase 2: fx = conv(s_da, We2) on halo-1 extended tile -> s_fx
    for (int i = tid; i < (TYF+2)*(TX+2); i += NT) {
        int ly = i / (TX+2), lx = i % (TX+2);
        int gy = y0 + ly - 1, gx = x0 + lx - 1;
        float a0 = 0.f, a1 = 0.f, a2 = 0.f, a3 = 0.f;
        float a4 = 0.f, a5 = 0.f, a6 = 0.f, a7 = 0.f;
        if (gy >= 0 && gy < HH && gx >= 0 && gx < WW) {
            #pragma unroll
            for (int c = 0; c < CC; c++) {
                #pragma unroll
                for (int k = 0; k < 9; k++) {
                    float v = SDA(c, ly + k/3, lx + k%3);
                    float4 wa = *(const float4*)&s_We2[c*72 + k*8];
                    float4 wb = *(const float4*)&s_We2[c*72 + k*8 + 4];
                    a0 = fmaf(v, wa.x, a0); a1 = fmaf(v, wa.y, a1);
                    a2 = fmaf(v, wa.z, a2); a3 = fmaf(v, wa.w, a3);
                    a4 = fmaf(v, wb.x, a4); a5 = fmaf(v, wb.y, a5);
                    a6 = fmaf(v, wb.z, a6); a7 = fmaf(v, wb.w, a7);
                }
            }
        }
        SFX(0, ly, lx) = a0; SFX(1, ly, lx) = a1;
        SFX(2, ly, lx) = a2; SFX(3, ly, lx) = a3;
        SFX(4, ly, lx) = a4; SFX(5, ly, lx) = a5;
        SFX(6, ly, lx) = a6; SFX(7, ly, lx) = a7;
    }
    __syncthreads();   // s_da fully consumed

    // phase 2b: load f halo-1 into the aliased buffer, MLP-4 batched
    #pragma unroll 1
    for (int base = tid; base < NB_F; base += NT*4) {
        float v[4];
        #pragma unroll
        for (int u = 0; u < 4; u++) {
            int i = base + u*NT;
            v[u] = 0.f;
            if (i < NB_F) {
                int c  = i / ((TYF+2)*(TX+2));
                int r  = i % ((TYF+2)*(TX+2));
                int ly = r / (TX+2), lx = r % (TX+2);
                int gy = y0 + ly - 1, gx = x0 + lx - 1;
                if (gy >= 0 && gy < HH && gx >= 0 && gx < WW)
                    v[u] = fb[((size_t)c*HH + gy)*WW + gx];
            }
        }
        #pragma unroll
        for (int u = 0; u < 4; u++) {
            int i = base + u*NT;
            if (i < NB_F) s_f[i] = v[u];
        }
    }
    __syncthreads();

    // phase 3: grouped paconv + blend; 2 core pixels/thread (split pairing)
    const int tyA = tid / TX, tx = tid % TX;
    const int tyB = tyA + TYH;
    const int gx = x0 + tx;
    const int gyA = y0 + tyA, gyB = y0 + tyB;
    const float x1A = SX1(tyA+2, tx+2);
    const float x1B = SX1(tyB+2, tx+2);
    float* dout = &g_d1[dst][0] + (size_t)b * CC * HH * WW;

    #pragma unroll
    for (int g = 0; g < CC; g++) {
        const float cfA  = SF (g, tyA+1, tx+1);
        const float cfxA = SFX(g, tyA+1, tx+1);
        const float cfB  = SF (g, tyB+1, tx+1);
        const float cfxB = SFX(g, tyB+1, tx+1);
        float w0A = 0.f, w1A = 0.f, w0B = 0.f, w1B = 0.f;
        #pragma unroll
        for (int k = 0; k < 9; k++) {
            const int dy = k/3, dx = k%3;
            float4 w = s_Wg4[g*9 + k];
            float pfA  = SF (g, tyA+dy, tx+dx);
            float pfxA = SFX(g, tyA+dy, tx+dx);
            float dfA = pfA - cfA, dfxA = pfxA - cfxA;
            float kernA = __expf(-0.5f * fmaf(dfA, dfA, dfxA*dfxA));
            w0A = fmaf(kernA, fmaf(pfA, w.x, pfxA * w.y), w0A);
            w1A = fmaf(kernA, fmaf(pfA, w.z, pfxA * w.w), w1A);

            float pfB  = SF (g, tyB+dy, tx+dx);
            float pfxB = SFX(g, tyB+dy, tx+dx);
            float dfB = pfB - cfB, dfxB = pfxB - cfxB;
            float kernB = __expf(-0.5f * fmaf(dfB, dfB, dfxB*dfxB));
            w0B = fmaf(kernB, fmaf(pfB, w.x, pfxB * w.y), w0B);
            w1B = fmaf(kernB, fmaf(pfB, w.z, pfxB * w.w), w1B);
        }
        float sA = 1.f / (1.f + __expf(-2.0f * (w1A - w0A)));
        float sB = 1.f / (1.f + __expf(-2.0f * (w1B - w0B)));
        float dA = d1b[((size_t)g*HH + gyA)*WW + gx];
        float dB = d1b[((size_t)g*HH + gyB)*WW + gx];
        dout[((size_t)g*HH + gyA)*WW + gx] = dA + sA * (x1A - dA);
        dout[((size_t)g*HH + gyB)*WW + gx] = dB + sB * (x1B - dB);
    }
}

// ---------------------------------------------------------------------------
extern "C" void kernel_launch(void* const* d_in, const int* in_sizes, int n_in,
                              void* d_out, int out_size)
{
    const float* d1  = (const float*)d_in[0];
    const float* We  = (const float*)d_in[1];
    const float* Wp  = (const float*)d_in[2];
    const float* We2 = (const float*)d_in[3];
    const float* Wg  = (const float*)d_in[4];
    float* out = (float*)d_out;

    cudaFuncSetAttribute((const void*)k_stage_b,
                         cudaFuncAttributeMaxDynamicSharedMemorySize,
                         SMEM_B_BYTES);

    dim3 grid(WW/TX, HH/TYF, BB);
    const int HW = HH * WW;
    const int WSZ = CC*CC*9;
    const int GSZ = CC*2*9*2;

    k_stage_a<<<grid, NT>>>(d1, 0, We + 0*WSZ, Wp + 0*WSZ, out, 0);
    k_stage_b<<<grid, NT, SMEM_B_BYTES>>>(d1, 0, 0, out + 0*HW, We2 + 0*WSZ, Wg + 0*GSZ);

    k_stage_a<<<grid, NT>>>(nullptr, 0, We + 1*WSZ, Wp + 1*WSZ, out, 1);
    k_stage_b<<<grid, NT, SMEM_B_BYTES>>>(nullptr, 0, 1, out + 1*HW, We2 + 1*WSZ, Wg + 1*GSZ);

    k_stage_a<<<grid, NT>>>(nullptr, 1, We + 2*WSZ, Wp + 2*WSZ, out, 2);
    k_stage_b<<<grid, NT, SMEM_B_BYTES>>>(nullptr, 1, 0, out + 2*HW, We2 + 2*WSZ, Wg + 2*GSZ);

    k_stage_a<<<grid, NT>>>(nullptr, 0, We + 3*WSZ, Wp + 3*WSZ, out, 3);
}